// round 16
// baseline (speedup 1.0000x reference)
#include <cuda_runtime.h>
#include <cuda_fp16.h>
#include <math.h>
#include <stdint.h>

#define B   8
#define C   256
#define P   1024
#define CIN 768
#define TC  512
#define G   32
#define CG  24
#define CH  64
#define NH  4

#define KTILE 64
#define KSPLIT 2
#define TILES_PER_CTA (P / KTILE / KSPLIT)   // 8

// ---------------- mma/ldmatrix helpers (baseline PTX, sm_103-safe) ----------------
__device__ __forceinline__ uint32_t smem_u32(const void* p) {
    uint32_t a; asm("{ .reg .u64 t; cvta.to.shared.u64 t, %1; cvt.u32.u64 %0, t; }" : "=r"(a) : "l"(p));
    return a;
}
__device__ __forceinline__ void ldm_x4(uint32_t& r0, uint32_t& r1, uint32_t& r2, uint32_t& r3, uint32_t addr) {
    asm volatile("ldmatrix.sync.aligned.m8n8.x4.shared.b16 {%0,%1,%2,%3}, [%4];"
                 : "=r"(r0), "=r"(r1), "=r"(r2), "=r"(r3) : "r"(addr));
}
__device__ __forceinline__ void ldm_x4t(uint32_t& r0, uint32_t& r1, uint32_t& r2, uint32_t& r3, uint32_t addr) {
    asm volatile("ldmatrix.sync.aligned.m8n8.x4.trans.shared.b16 {%0,%1,%2,%3}, [%4];"
                 : "=r"(r0), "=r"(r1), "=r"(r2), "=r"(r3) : "r"(addr));
}
__device__ __forceinline__ void mma16816(float* c, const uint32_t* a, uint32_t b0, uint32_t b1) {
    asm volatile("mma.sync.aligned.m16n8k16.row.col.f32.f16.f16.f32 "
                 "{%0,%1,%2,%3}, {%4,%5,%6,%7}, {%8,%9}, {%0,%1,%2,%3};"
                 : "+f"(c[0]), "+f"(c[1]), "+f"(c[2]), "+f"(c[3])
                 : "r"(a[0]), "r"(a[1]), "r"(a[2]), "r"(a[3]), "r"(b0), "r"(b1));
}
__device__ __forceinline__ uint32_t f16pack(float lo, float hi) {
    uint32_t r; asm("cvt.rn.f16x2.f32 %0, %1, %2;" : "=r"(r) : "f"(hi), "f"(lo)); return r;
}
__device__ __forceinline__ uint32_t ex2h2(uint32_t a) {
    uint32_t r; asm("ex2.approx.f16x2 %0, %1;" : "=r"(r) : "r"(a)); return r;
}
__device__ __forceinline__ uint32_t hadd2(uint32_t a, uint32_t b) {
    uint32_t r; asm("add.rn.f16x2 %0, %1, %2;" : "=r"(r) : "r"(a), "r"(b)); return r;
}
__device__ __forceinline__ float2 h2f2(uint32_t a) {
    __half2 h = *reinterpret_cast<__half2*>(&a);
    return __half22float2(h);
}
__device__ __forceinline__ void cp16(uint32_t dst, const void* src) {
    asm volatile("cp.async.cg.shared.global [%0], [%1], 16;" :: "r"(dst), "l"(src));
}
#define CP_COMMIT() asm volatile("cp.async.commit_group;" ::: "memory")
#define CP_WAIT(n)  asm volatile("cp.async.wait_group %0;" :: "n"(n) : "memory")
#define SWZ(o) ((o) ^ (((o) >> 3) & 0x70))

// ---------------- scratch ----------------
__device__ float g_mu[B * G];
__device__ float g_rs[B * G];
__device__ float g_cbias[3][B][C];
__device__ __align__(16) __half g_xb[B * C * P];   // f16(x*A) [b][c][p]
__device__ __align__(16) __half g_wb[3 * C * C];   // f16(W)   [j][c][d]
__device__ __align__(16) __half g_qb[B * P * C];   // [b][p][d], pre-scaled log2e/8
__device__ __align__(16) __half g_kb[B * P * C];
__device__ __align__(16) __half g_vb[B * P * C];
__device__ __align__(16) float g_opart[1024 * 4096]; // [ctid][64d][64q] unnormalized
__device__ __align__(16) float g_lpart[1024 * 64];   // [ctid][64q]

// ---------------- kernel 1: GroupNorm stats ----------------
__global__ void gn_stats(const float* __restrict__ x, const float* __restrict__ text) {
    int bg = blockIdx.x;
    int b = bg / G, g = bg % G;
    int t = threadIdx.x;          // 256 threads
    float s = 0.f, ss = 0.f;
    for (int i = t; i < CG * 256; i += 256) {
        int cl = i >> 8, p4 = i & 255;
        int c = g * CG + cl;
        if (c < C) {
            float4 v = *reinterpret_cast<const float4*>(x + (((size_t)(b * C + c)) << 10) + p4 * 4);
            s  += v.x + v.y + v.z + v.w;
            ss += v.x * v.x + v.y * v.y + v.z * v.z + v.w * v.w;
        } else if (p4 == 0) {
            float v = text[b * TC + (c - C)];
            s  += 1024.f * v;
            ss += 1024.f * v * v;
        }
    }
    __shared__ float sh1[256], sh2[256];
    sh1[t] = s; sh2[t] = ss;
    __syncthreads();
    for (int o = 128; o > 0; o >>= 1) {
        if (t < o) { sh1[t] += sh1[t + o]; sh2[t] += sh2[t + o]; }
        __syncthreads();
    }
    if (t == 0) {
        float n = (float)(CG * P);
        float mu = sh1[0] / n;
        float var = sh2[0] / n - mu * mu;
        g_mu[bg] = mu;
        g_rs[bg] = rsqrtf(var + 1e-6f);
    }
}

// ---------------- kernel 2: fused const_bias + conv_w + conv_x ----------------
__global__ void __launch_bounds__(256) prep_all(const float* __restrict__ x,
                                                const float* __restrict__ text,
                                                const float* __restrict__ gamma,
                                                const float* __restrict__ beta,
                                                const float* __restrict__ W0, const float* __restrict__ b0,
                                                const float* __restrict__ W1, const float* __restrict__ b1,
                                                const float* __restrict__ W2, const float* __restrict__ b2) {
    int blk = blockIdx.x;
    int t = threadIdx.x;
    if (blk < 24) {
        int j = blk >> 3, b = blk & 7;
        __shared__ float esh[CIN];
        for (int c = t; c < CIN; c += 256) {
            int g = c / CG;
            float rs = g_rs[b * G + g], mu = g_mu[b * G + g];
            float A = rs * gamma[c];
            float e = beta[c] - mu * A;
            if (c >= C) e += A * text[b * TC + (c - C)];
            esh[c] = e;
        }
        __syncthreads();
        const float* Wj = (j == 0) ? W0 : (j == 1) ? W1 : W2;
        const float* bj = (j == 0) ? b0 : (j == 1) ? b1 : b2;
        float acc = bj[t];
#pragma unroll 4
        for (int c = 0; c < CIN; c++) acc += esh[c] * Wj[c * C + t];
        g_cbias[j][b][t] = acc;
    } else if (blk < 216) {
        int idx = (blk - 24) * 256 + t;        // 49152 items
        int row = idx >> 6, i = idx & 63;
        int j = row >> 8, c = row & 255;
        const float* Wj = (j == 0) ? W0 : (j == 1) ? W1 : W2;
        float4 v = reinterpret_cast<const float4*>(Wj + (size_t)c * C)[i];
        uint2 u;
        u.x = f16pack(v.x, v.y);
        u.y = f16pack(v.z, v.w);
        reinterpret_cast<uint2*>(g_wb + (size_t)row * C)[i] = u;
    } else {
        const int total = B * C * 256;            // 524288 float4 chunks
        for (int idx = (blk - 216) * 256 + t; idx < total; idx += 1024 * 256) {
            int bc = idx >> 8;
            int b = bc >> 8, c = bc & 255;
            float A = g_rs[b * G + c / CG] * gamma[c];
            float4 v = reinterpret_cast<const float4*>(x)[idx];
            uint2 u;
            u.x = f16pack(v.x * A, v.y * A);
            u.y = f16pack(v.z * A, v.w * A);
            reinterpret_cast<uint2*>(g_xb)[idx] = u;
        }
    }
}

// ---------------- kernel 3: QKV GEMM, M=128 N=64 per CTA, 3-stage pipeline ----------------
#define LDAX 136
#define LDW  72
__global__ void __launch_bounds__(128, 3) qkv_mma() {
    __shared__ __align__(16) __half sa[3][32][LDAX];  // 25.5KB
    __shared__ __align__(16) __half sw[3][32][LDW];   // 13.5KB
    int tid = threadIdx.x;
    int wid = tid >> 5, lane = tid & 31;
    int grp = lane >> 3, lr = lane & 7;
    int gr = lane >> 2, cl = lane & 3;
    int b = blockIdx.z;
    int p0 = blockIdx.x * 128;
    int jd = blockIdx.y;            // 0..11
    int j = jd >> 2;
    int d0 = (jd & 3) * 64;

    uint32_t sa_b[3], sw_b[3];
#pragma unroll
    for (int i = 0; i < 3; i++) {
        sa_b[i] = smem_u32(&sa[i][0][0]);
        sw_b[i] = smem_u32(&sw[i][0][0]);
    }
    const __half* xb = g_xb + (size_t)b * C * P;
    const __half* wj = g_wb + (size_t)j * C * C;

    float acc[2][8][4];
#pragma unroll
    for (int mg = 0; mg < 2; mg++)
#pragma unroll
        for (int n = 0; n < 8; n++)
#pragma unroll
            for (int i = 0; i < 4; i++) acc[mg][n][i] = 0.f;

#pragma unroll
    for (int pc = 0; pc < 3; pc++) {
        int c0 = pc * 32;
#pragma unroll
        for (int it = 0; it < 4; it++) {
            int lin = it * 128 + tid, cr = lin >> 4, p16 = (lin & 15) * 8;
            cp16(sa_b[pc] + (uint32_t)(cr * LDAX + p16) * 2, xb + (size_t)(c0 + cr) * P + p0 + p16);
        }
#pragma unroll
        for (int it = 0; it < 2; it++) {
            int lin = it * 128 + tid, cr = lin >> 3, d8 = (lin & 7) * 8;
            cp16(sw_b[pc] + (uint32_t)(cr * LDW + d8) * 2, wj + (size_t)(c0 + cr) * C + d0 + d8);
        }
        CP_COMMIT();
    }

    for (int ch = 0; ch < 8; ch++) {
        if (ch <= 5) { CP_WAIT(2); } else if (ch == 6) { CP_WAIT(1); } else { CP_WAIT(0); }
        __syncthreads();
        uint32_t sab = sa_b[ch % 3], swb = sw_b[ch % 3];
#pragma unroll
        for (int ks = 0; ks < 2; ks++) {
            int kb = ks * 16;
            uint32_t a[2][4];
#pragma unroll
            for (int mg = 0; mg < 2; mg++) {
                int row = kb + ((grp >> 1) ? 8 : 0) + lr;
                int col = wid * 32 + mg * 16 + ((grp & 1) ? 8 : 0);
                ldm_x4t(a[mg][0], a[mg][1], a[mg][2], a[mg][3],
                        sab + (uint32_t)(row * LDAX + col) * 2);
            }
#pragma unroll
            for (int nn = 0; nn < 4; nn++) {
                uint32_t r0, r1, r2, r3;
                int row = kb + ((grp & 1) ? 8 : 0) + lr;
                int col = nn * 16 + ((grp >> 1) ? 8 : 0);
                ldm_x4t(r0, r1, r2, r3, swb + (uint32_t)(row * LDW + col) * 2);
                mma16816(acc[0][nn * 2],     a[0], r0, r1);
                mma16816(acc[0][nn * 2 + 1], a[0], r2, r3);
                mma16816(acc[1][nn * 2],     a[1], r0, r1);
                mma16816(acc[1][nn * 2 + 1], a[1], r2, r3);
            }
        }
        __syncthreads();
        if (ch + 3 < 8) {
            int c0 = (ch + 3) * 32;
            int nb = ch % 3;
#pragma unroll
            for (int it = 0; it < 4; it++) {
                int lin = it * 128 + tid, cr = lin >> 4, p16 = (lin & 15) * 8;
                cp16(sa_b[nb] + (uint32_t)(cr * LDAX + p16) * 2, xb + (size_t)(c0 + cr) * P + p0 + p16);
            }
#pragma unroll
            for (int it = 0; it < 2; it++) {
                int lin = it * 128 + tid, cr = lin >> 3, d8 = (lin & 7) * 8;
                cp16(sw_b[nb] + (uint32_t)(cr * LDW + d8) * 2, wj + (size_t)(c0 + cr) * C + d0 + d8);
            }
            CP_COMMIT();
        }
    }

    const float QSCL = 1.4426950408889634f * 0.125f;
    float s = (j == 0) ? QSCL : 1.f;
    __half* dst = (j == 0) ? g_qb : (j == 1) ? g_kb : g_vb;
#pragma unroll
    for (int mg = 0; mg < 2; mg++) {
        int p_lo = p0 + wid * 32 + mg * 16 + gr;
#pragma unroll
        for (int nt = 0; nt < 8; nt++) {
            int d = d0 + nt * 8 + 2 * cl;
            float cb0 = g_cbias[j][b][d], cb1 = g_cbias[j][b][d + 1];
            uint32_t lo = f16pack((acc[mg][nt][0] + cb0) * s, (acc[mg][nt][1] + cb1) * s);
            uint32_t hi = f16pack((acc[mg][nt][2] + cb0) * s, (acc[mg][nt][3] + cb1) * s);
            *reinterpret_cast<uint32_t*>(dst + ((size_t)(b * P) + p_lo) * C + d) = lo;
            *reinterpret_cast<uint32_t*>(dst + ((size_t)(b * P) + p_lo + 8) * C + d) = hi;
        }
    }
}

// ---------------- kernel 4: split-K flash attention (partials) ----------------
// grid (16 qtiles, 64 = head*2+ks). Each CTA: 64 q rows x 512 keys (8 tiles).
// Writes unnormalized o [64d][64q] f32 + l [64q] to scratch.
#define KVB 16384
#define STOT 32768

__global__ void __launch_bounds__(64, 6) attn_part(float* __restrict__ dummy) {
    __shared__ __align__(128) char smem[STOT];
    uint32_t sb = smem_u32(smem);
    int tid = threadIdx.x;
    int wid = tid >> 5, lane = tid & 31;
    int grp = lane >> 3, lr = lane & 7;
    int by = blockIdx.y;            // head*2 + ks
    int head = by >> 1, ks = by & 1;
    int b = head >> 2, h = head & 3;
    int q0 = blockIdx.x * 64;
    int ctid = by * 16 + blockIdx.x;
    int key0 = ks * (P / KSPLIT);

    const char* qsrc  = (const char*)(g_qb + ((size_t)(b * P) + q0) * C + h * CH);
    const char* kbase = (const char*)(g_kb + ((size_t)(b * P) + key0) * C + h * CH);
    const char* vbase = (const char*)(g_vb + ((size_t)(b * P) + key0) * C + h * CH);

    // stage Q (8KB) into buf0, read fragments, release
#pragma unroll
    for (int it = 0; it < 8; it++) {
        int lin = it * 64 + tid;
        int row = lin >> 3, ch = lin & 7;
        cp16(sb + SWZ(row * 128 + ch * 16), qsrc + (size_t)row * (C * 2) + ch * 16);
    }
    CP_COMMIT();
    CP_WAIT(0);
    __syncthreads();

    uint32_t qa[2][4][4];
#pragma unroll
    for (int mg = 0; mg < 2; mg++)
#pragma unroll
        for (int kc = 0; kc < 4; kc++) {
            int row = wid * 32 + mg * 16 + ((grp & 1) ? 8 : 0) + lr;
            int col = kc * 16 + ((grp >> 1) ? 8 : 0);
            ldm_x4(qa[mg][kc][0], qa[mg][kc][1], qa[mg][kc][2], qa[mg][kc][3],
                   sb + SWZ(row * 128 + col * 2));
        }
    __syncthreads();    // buf0 free

    // issue K/V tiles 0 and 1
    {
        int row = tid >> 3, ch = tid & 7;   // row 0..7
#pragma unroll
        for (int tt = 0; tt < 2; tt++) {
            uint32_t base = sb + tt * KVB;
            int t0 = tt * KTILE;
#pragma unroll
            for (int qr = 0; qr < 8; qr++) {
                int r = row + qr * 8;
                uint32_t so2 = SWZ(r * 128 + ch * 16);
                cp16(base + so2, kbase + (size_t)(t0 + r) * (C * 2) + ch * 16);
                cp16(base + 8192 + so2, vbase + (size_t)(t0 + r) * (C * 2) + ch * 16);
            }
            CP_COMMIT();
        }
    }

    float o0[8][4], o1[8][4];
#pragma unroll
    for (int j = 0; j < 8; j++)
#pragma unroll
        for (int i = 0; i < 4; i++) { o0[j][i] = 0.f; o1[j][i] = 0.f; }
    float l0_lo = 0.f, l0_hi = 0.f, l1_lo = 0.f, l1_hi = 0.f;

    for (int t = 0; t < TILES_PER_CTA; t++) {
        if (t < TILES_PER_CTA - 1) { CP_WAIT(1); } else { CP_WAIT(0); }
        __syncthreads();        // tile t resident

        uint32_t ksm = sb + (t & 1) * KVB;
        uint32_t vsm = ksm + 8192;

        // S = Q K^T, f16x2 exp, P fragments
        uint32_t pfr0[4][4], pfr1[4][4];
        uint32_t ll0 = 0, lh0 = 0, ll1 = 0, lh1 = 0;
#pragma unroll
        for (int np = 0; np < 4; np++) {
            float s0[2][4], s1[2][4];
#pragma unroll
            for (int i = 0; i < 4; i++) { s0[0][i] = s0[1][i] = s1[0][i] = s1[1][i] = 0.f; }
#pragma unroll
            for (int kc = 0; kc < 4; kc++) {
                int row = np * 16 + ((grp >> 1) ? 8 : 0) + lr;   // key
                int col = kc * 16 + ((grp & 1) ? 8 : 0);         // d
                uint32_t r0, r1, r2, r3;
                ldm_x4(r0, r1, r2, r3, ksm + SWZ(row * 128 + col * 2));
                mma16816(s0[0], qa[0][kc], r0, r1);
                mma16816(s0[1], qa[0][kc], r2, r3);
                mma16816(s1[0], qa[1][kc], r0, r1);
                mma16816(s1[1], qa[1][kc], r2, r3);
            }
            pfr0[np][0] = ex2h2(f16pack(s0[0][0], s0[0][1]));
            pfr0[np][1] = ex2h2(f16pack(s0[0][2], s0[0][3]));
            pfr0[np][2] = ex2h2(f16pack(s0[1][0], s0[1][1]));
            pfr0[np][3] = ex2h2(f16pack(s0[1][2], s0[1][3]));
            ll0 = hadd2(ll0, hadd2(pfr0[np][0], pfr0[np][2]));
            lh0 = hadd2(lh0, hadd2(pfr0[np][1], pfr0[np][3]));
            pfr1[np][0] = ex2h2(f16pack(s1[0][0], s1[0][1]));
            pfr1[np][1] = ex2h2(f16pack(s1[0][2], s1[0][3]));
            pfr1[np][2] = ex2h2(f16pack(s1[1][0], s1[1][1]));
            pfr1[np][3] = ex2h2(f16pack(s1[1][2], s1[1][3]));
            ll1 = hadd2(ll1, hadd2(pfr1[np][0], pfr1[np][2]));
            lh1 = hadd2(lh1, hadd2(pfr1[np][1], pfr1[np][3]));
        }
        {
            float2 f;
            f = h2f2(ll0); l0_lo += f.x + f.y;
            f = h2f2(lh0); l0_hi += f.x + f.y;
            f = h2f2(ll1); l1_lo += f.x + f.y;
            f = h2f2(lh1); l1_hi += f.x + f.y;
        }

        // O += P V
#pragma unroll
        for (int np = 0; np < 4; np++) {
#pragma unroll
            for (int kc = 0; kc < 4; kc++) {
                int row = kc * 16 + ((grp & 1) ? 8 : 0) + lr;    // key
                int col = np * 16 + ((grp >> 1) ? 8 : 0);        // d
                uint32_t r0, r1, r2, r3;
                ldm_x4t(r0, r1, r2, r3, vsm + SWZ(row * 128 + col * 2));
                mma16816(o0[2 * np],     pfr0[kc], r0, r1);
                mma16816(o0[2 * np + 1], pfr0[kc], r2, r3);
                mma16816(o1[2 * np],     pfr1[kc], r0, r1);
                mma16816(o1[2 * np + 1], pfr1[kc], r2, r3);
            }
        }

        __syncthreads();        // all warps done reading buf (t&1)
        if (t + 2 < TILES_PER_CTA) {
            int t0 = (t + 2) * KTILE;
            uint32_t base = sb + (t & 1) * KVB;
            int row = tid >> 3, ch = tid & 7;
#pragma unroll
            for (int qr = 0; qr < 8; qr++) {
                int r = row + qr * 8;
                uint32_t so2 = SWZ(r * 128 + ch * 16);
                cp16(base + so2, kbase + (size_t)(t0 + r) * (C * 2) + ch * 16);
                cp16(base + 8192 + so2, vbase + (size_t)(t0 + r) * (C * 2) + ch * 16);
            }
            CP_COMMIT();
        }
    }

    // quad-reduce l
    l0_lo += __shfl_xor_sync(0xFFFFFFFF, l0_lo, 1);
    l0_lo += __shfl_xor_sync(0xFFFFFFFF, l0_lo, 2);
    l0_hi += __shfl_xor_sync(0xFFFFFFFF, l0_hi, 1);
    l0_hi += __shfl_xor_sync(0xFFFFFFFF, l0_hi, 2);
    l1_lo += __shfl_xor_sync(0xFFFFFFFF, l1_lo, 1);
    l1_lo += __shfl_xor_sync(0xFFFFFFFF, l1_lo, 2);
    l1_hi += __shfl_xor_sync(0xFFFFFFFF, l1_hi, 1);
    l1_hi += __shfl_xor_sync(0xFFFFFFFF, l1_hi, 2);

    // write l partials
    float* lp = g_lpart + (size_t)ctid * 64;
    int rq = lane >> 2;
    if ((lane & 3) == 0) {
        int r0 = wid * 32 + rq;
        lp[r0]      = l0_lo;
        lp[r0 + 8]  = l0_hi;
        lp[r0 + 16] = l1_lo;
        lp[r0 + 24] = l1_hi;
    }

    // stage unnormalized O [d][q], write to scratch
    float* so = reinterpret_cast<float*>(smem);   // 16KB
    int dc = 2 * (lane & 3);
#pragma unroll
    for (int mg = 0; mg < 2; mg++) {
        int r_lo = wid * 32 + mg * 16 + rq;
        int r_hi = r_lo + 8;
#pragma unroll
        for (int j = 0; j < 8; j++) {
            int d = 8 * j + dc;
            float (*oo)[4] = mg ? o1 : o0;
            so[d * 64 + r_lo]       = oo[j][0];
            so[(d + 1) * 64 + r_lo] = oo[j][1];
            so[d * 64 + r_hi]       = oo[j][2];
            so[(d + 1) * 64 + r_hi] = oo[j][3];
        }
    }
    __syncthreads();

    float4* op = reinterpret_cast<float4*>(g_opart + (size_t)ctid * 4096);
    const float4* sov = reinterpret_cast<const float4*>(so);
#pragma unroll
    for (int it = 0; it < 16; it++) op[it * 64 + tid] = sov[it * 64 + tid];
    (void)dummy;
}

// ---------------- kernel 5: split-K merge + residual ----------------
__global__ void __launch_bounds__(128) attn_merge(const float* __restrict__ x,
                                                  float* __restrict__ out) {
    int qt = blockIdx.x;            // 0..15
    int head = blockIdx.y;          // 0..31
    int b = head >> 2, h = head & 3;
    int q0 = qt * 64;
    int ct0 = (head * 2 + 0) * 16 + qt;
    int ct1 = (head * 2 + 1) * 16 + qt;
    int tid = threadIdx.x;

    __shared__ float inv[64];
    if (tid < 64)
        inv[tid] = 1.f / (g_lpart[(size_t)ct0 * 64 + tid] + g_lpart[(size_t)ct1 * 64 + tid]);
    __syncthreads();

    const float* oA = g_opart + (size_t)ct0 * 4096;
    const float* oB = g_opart + (size_t)ct1 * 4096;
    size_t base = ((size_t)(b * C) + h * CH) * P + q0;
#pragma unroll
    for (int it = 0; it < 32; it++) {
        int lin = it * 128 + tid;
        int d = lin >> 6, qq = lin & 63;
        size_t idx = base + (size_t)d * P + qq;
        out[idx] = x[idx] + (oA[lin] + oB[lin]) * inv[qq];
    }
}

// ---------------- launch ----------------
extern "C" void kernel_launch(void* const* d_in, const int* in_sizes, int n_in,
                              void* d_out, int out_size) {
    const float* x     = (const float*)d_in[0];
    const float* text  = (const float*)d_in[1];
    const float* gamma = (const float*)d_in[2];
    const float* beta  = (const float*)d_in[3];
    const float* W0    = (const float*)d_in[4];
    const float* b0    = (const float*)d_in[5];
    const float* W1    = (const float*)d_in[6];
    const float* b1    = (const float*)d_in[7];
    const float* W2    = (const float*)d_in[8];
    const float* b2    = (const float*)d_in[9];
    float* out = (float*)d_out;

    gn_stats<<<B * G, 256>>>(x, text);
    prep_all<<<1240, 256>>>(x, text, gamma, beta, W0, b0, W1, b1, W2, b2);
    qkv_mma<<<dim3(P / 128, 12, B), 128>>>();
    attn_part<<<dim3(16, 64), 64>>>(out);
    attn_merge<<<dim3(16, 32), 128>>>(x, out);
}

// round 17
// speedup vs baseline: 1.1515x; 1.1515x over previous
#include <cuda_runtime.h>
#include <cuda_fp16.h>
#include <math.h>
#include <stdint.h>

#define B   8
#define C   256
#define P   1024
#define CIN 768
#define TC  512
#define G   32
#define CG  24
#define CH  64
#define NH  4

#define KTILE 64
#define NKT   (P / KTILE)   // 16

// ---------------- mma/ldmatrix helpers (baseline PTX, sm_103-safe) ----------------
__device__ __forceinline__ uint32_t smem_u32(const void* p) {
    uint32_t a; asm("{ .reg .u64 t; cvta.to.shared.u64 t, %1; cvt.u32.u64 %0, t; }" : "=r"(a) : "l"(p));
    return a;
}
__device__ __forceinline__ void ldm_x4(uint32_t& r0, uint32_t& r1, uint32_t& r2, uint32_t& r3, uint32_t addr) {
    asm volatile("ldmatrix.sync.aligned.m8n8.x4.shared.b16 {%0,%1,%2,%3}, [%4];"
                 : "=r"(r0), "=r"(r1), "=r"(r2), "=r"(r3) : "r"(addr));
}
__device__ __forceinline__ void ldm_x4t(uint32_t& r0, uint32_t& r1, uint32_t& r2, uint32_t& r3, uint32_t addr) {
    asm volatile("ldmatrix.sync.aligned.m8n8.x4.trans.shared.b16 {%0,%1,%2,%3}, [%4];"
                 : "=r"(r0), "=r"(r1), "=r"(r2), "=r"(r3) : "r"(addr));
}
__device__ __forceinline__ void mma16816(float* c, const uint32_t* a, uint32_t b0, uint32_t b1) {
    asm volatile("mma.sync.aligned.m16n8k16.row.col.f32.f16.f16.f32 "
                 "{%0,%1,%2,%3}, {%4,%5,%6,%7}, {%8,%9}, {%0,%1,%2,%3};"
                 : "+f"(c[0]), "+f"(c[1]), "+f"(c[2]), "+f"(c[3])
                 : "r"(a[0]), "r"(a[1]), "r"(a[2]), "r"(a[3]), "r"(b0), "r"(b1));
}
__device__ __forceinline__ uint32_t f16pack(float lo, float hi) {
    uint32_t r; asm("cvt.rn.f16x2.f32 %0, %1, %2;" : "=r"(r) : "f"(hi), "f"(lo)); return r;
}
__device__ __forceinline__ uint32_t ex2h2(uint32_t a) {
    uint32_t r; asm("ex2.approx.f16x2 %0, %1;" : "=r"(r) : "r"(a)); return r;
}
__device__ __forceinline__ uint32_t hadd2(uint32_t a, uint32_t b) {
    uint32_t r; asm("add.rn.f16x2 %0, %1, %2;" : "=r"(r) : "r"(a), "r"(b)); return r;
}
__device__ __forceinline__ float2 h2f2(uint32_t a) {
    __half2 h = *reinterpret_cast<__half2*>(&a);
    return __half22float2(h);
}
__device__ __forceinline__ void cp16(uint32_t dst, const void* src) {
    asm volatile("cp.async.cg.shared.global [%0], [%1], 16;" :: "r"(dst), "l"(src));
}
#define CP_COMMIT() asm volatile("cp.async.commit_group;" ::: "memory")
#define CP_WAIT(n)  asm volatile("cp.async.wait_group %0;" :: "n"(n) : "memory")
#define SWZ(o) ((o) ^ (((o) >> 3) & 0x70))

// ---------------- scratch ----------------
__device__ float g_mu[B * G];
__device__ float g_rs[B * G];
__device__ float g_cbias[3][B][C];
__device__ __align__(16) __half g_xb[B * C * P];   // f16(x*A) [b][c][p]
__device__ __align__(16) __half g_wb[3 * C * C];   // f16(W)   [j][c][d]
__device__ __align__(16) __half g_qb[B * P * C];   // [b][p][d], pre-scaled log2e/8
__device__ __align__(16) __half g_kb[B * P * C];
__device__ __align__(16) __half g_vb[B * P * C];

// ---------------- kernel 1: GroupNorm stats ----------------
__global__ void gn_stats(const float* __restrict__ x, const float* __restrict__ text) {
    int bg = blockIdx.x;
    int b = bg / G, g = bg % G;
    int t = threadIdx.x;          // 256 threads
    float s = 0.f, ss = 0.f;
    for (int i = t; i < CG * 256; i += 256) {
        int cl = i >> 8, p4 = i & 255;
        int c = g * CG + cl;
        if (c < C) {
            float4 v = *reinterpret_cast<const float4*>(x + (((size_t)(b * C + c)) << 10) + p4 * 4);
            s  += v.x + v.y + v.z + v.w;
            ss += v.x * v.x + v.y * v.y + v.z * v.z + v.w * v.w;
        } else if (p4 == 0) {
            float v = text[b * TC + (c - C)];
            s  += 1024.f * v;
            ss += 1024.f * v * v;
        }
    }
    __shared__ float sh1[256], sh2[256];
    sh1[t] = s; sh2[t] = ss;
    __syncthreads();
    for (int o = 128; o > 0; o >>= 1) {
        if (t < o) { sh1[t] += sh1[t + o]; sh2[t] += sh2[t + o]; }
        __syncthreads();
    }
    if (t == 0) {
        float n = (float)(CG * P);
        float mu = sh1[0] / n;
        float var = sh2[0] / n - mu * mu;
        g_mu[bg] = mu;
        g_rs[bg] = rsqrtf(var + 1e-6f);
    }
}

// ---------------- kernel 2: fused const_bias + conv_w + conv_x ----------------
__global__ void __launch_bounds__(256) prep_all(const float* __restrict__ x,
                                                const float* __restrict__ text,
                                                const float* __restrict__ gamma,
                                                const float* __restrict__ beta,
                                                const float* __restrict__ W0, const float* __restrict__ b0,
                                                const float* __restrict__ W1, const float* __restrict__ b1,
                                                const float* __restrict__ W2, const float* __restrict__ b2) {
    int blk = blockIdx.x;
    int t = threadIdx.x;
    if (blk < 24) {
        int j = blk >> 3, b = blk & 7;
        __shared__ float esh[CIN];
        for (int c = t; c < CIN; c += 256) {
            int g = c / CG;
            float rs = g_rs[b * G + g], mu = g_mu[b * G + g];
            float A = rs * gamma[c];
            float e = beta[c] - mu * A;
            if (c >= C) e += A * text[b * TC + (c - C)];
            esh[c] = e;
        }
        __syncthreads();
        const float* Wj = (j == 0) ? W0 : (j == 1) ? W1 : W2;
        const float* bj = (j == 0) ? b0 : (j == 1) ? b1 : b2;
        float acc = bj[t];
#pragma unroll 4
        for (int c = 0; c < CIN; c++) acc += esh[c] * Wj[c * C + t];
        g_cbias[j][b][t] = acc;
    } else if (blk < 216) {
        int idx = (blk - 24) * 256 + t;        // 49152 items
        int row = idx >> 6, i = idx & 63;
        int j = row >> 8, c = row & 255;
        const float* Wj = (j == 0) ? W0 : (j == 1) ? W1 : W2;
        float4 v = reinterpret_cast<const float4*>(Wj + (size_t)c * C)[i];
        uint2 u;
        u.x = f16pack(v.x, v.y);
        u.y = f16pack(v.z, v.w);
        reinterpret_cast<uint2*>(g_wb + (size_t)row * C)[i] = u;
    } else {
        const int total = B * C * 256;            // 524288 float4 chunks
        for (int idx = (blk - 216) * 256 + t; idx < total; idx += 1024 * 256) {
            int bc = idx >> 8;
            int b = bc >> 8, c = bc & 255;
            float A = g_rs[b * G + c / CG] * gamma[c];
            float4 v = reinterpret_cast<const float4*>(x)[idx];
            uint2 u;
            u.x = f16pack(v.x * A, v.y * A);
            u.y = f16pack(v.z * A, v.w * A);
            reinterpret_cast<uint2*>(g_xb)[idx] = u;
        }
    }
}

// ---------------- kernel 3: QKV GEMM, M=128 N=64 per CTA, 3-stage pipeline ----------------
#define LDAX 136
#define LDW  72
__global__ void __launch_bounds__(128, 3) qkv_mma() {
    __shared__ __align__(16) __half sa[3][32][LDAX];  // 25.5KB
    __shared__ __align__(16) __half sw[3][32][LDW];   // 13.5KB
    int tid = threadIdx.x;
    int wid = tid >> 5, lane = tid & 31;
    int grp = lane >> 3, lr = lane & 7;
    int gr = lane >> 2, cl = lane & 3;
    int b = blockIdx.z;
    int p0 = blockIdx.x * 128;
    int jd = blockIdx.y;            // 0..11
    int j = jd >> 2;
    int d0 = (jd & 3) * 64;

    uint32_t sa_b[3], sw_b[3];
#pragma unroll
    for (int i = 0; i < 3; i++) {
        sa_b[i] = smem_u32(&sa[i][0][0]);
        sw_b[i] = smem_u32(&sw[i][0][0]);
    }
    const __half* xb = g_xb + (size_t)b * C * P;
    const __half* wj = g_wb + (size_t)j * C * C;

    float acc[2][8][4];
#pragma unroll
    for (int mg = 0; mg < 2; mg++)
#pragma unroll
        for (int n = 0; n < 8; n++)
#pragma unroll
            for (int i = 0; i < 4; i++) acc[mg][n][i] = 0.f;

#pragma unroll
    for (int pc = 0; pc < 3; pc++) {
        int c0 = pc * 32;
#pragma unroll
        for (int it = 0; it < 4; it++) {
            int lin = it * 128 + tid, cr = lin >> 4, p16 = (lin & 15) * 8;
            cp16(sa_b[pc] + (uint32_t)(cr * LDAX + p16) * 2, xb + (size_t)(c0 + cr) * P + p0 + p16);
        }
#pragma unroll
        for (int it = 0; it < 2; it++) {
            int lin = it * 128 + tid, cr = lin >> 3, d8 = (lin & 7) * 8;
            cp16(sw_b[pc] + (uint32_t)(cr * LDW + d8) * 2, wj + (size_t)(c0 + cr) * C + d0 + d8);
        }
        CP_COMMIT();
    }

    for (int ch = 0; ch < 8; ch++) {
        if (ch <= 5) { CP_WAIT(2); } else if (ch == 6) { CP_WAIT(1); } else { CP_WAIT(0); }
        __syncthreads();
        uint32_t sab = sa_b[ch % 3], swb = sw_b[ch % 3];
#pragma unroll
        for (int ks = 0; ks < 2; ks++) {
            int kb = ks * 16;
            uint32_t a[2][4];
#pragma unroll
            for (int mg = 0; mg < 2; mg++) {
                int row = kb + ((grp >> 1) ? 8 : 0) + lr;
                int col = wid * 32 + mg * 16 + ((grp & 1) ? 8 : 0);
                ldm_x4t(a[mg][0], a[mg][1], a[mg][2], a[mg][3],
                        sab + (uint32_t)(row * LDAX + col) * 2);
            }
#pragma unroll
            for (int nn = 0; nn < 4; nn++) {
                uint32_t r0, r1, r2, r3;
                int row = kb + ((grp & 1) ? 8 : 0) + lr;
                int col = nn * 16 + ((grp >> 1) ? 8 : 0);
                ldm_x4t(r0, r1, r2, r3, swb + (uint32_t)(row * LDW + col) * 2);
                mma16816(acc[0][nn * 2],     a[0], r0, r1);
                mma16816(acc[0][nn * 2 + 1], a[0], r2, r3);
                mma16816(acc[1][nn * 2],     a[1], r0, r1);
                mma16816(acc[1][nn * 2 + 1], a[1], r2, r3);
            }
        }
        __syncthreads();
        if (ch + 3 < 8) {
            int c0 = (ch + 3) * 32;
            int nb = ch % 3;
#pragma unroll
            for (int it = 0; it < 4; it++) {
                int lin = it * 128 + tid, cr = lin >> 4, p16 = (lin & 15) * 8;
                cp16(sa_b[nb] + (uint32_t)(cr * LDAX + p16) * 2, xb + (size_t)(c0 + cr) * P + p0 + p16);
            }
#pragma unroll
            for (int it = 0; it < 2; it++) {
                int lin = it * 128 + tid, cr = lin >> 3, d8 = (lin & 7) * 8;
                cp16(sw_b[nb] + (uint32_t)(cr * LDW + d8) * 2, wj + (size_t)(c0 + cr) * C + d0 + d8);
            }
            CP_COMMIT();
        }
    }

    const float QSCL = 1.4426950408889634f * 0.125f;
    float s = (j == 0) ? QSCL : 1.f;
    __half* dst = (j == 0) ? g_qb : (j == 1) ? g_kb : g_vb;
#pragma unroll
    for (int mg = 0; mg < 2; mg++) {
        int p_lo = p0 + wid * 32 + mg * 16 + gr;
#pragma unroll
        for (int nt = 0; nt < 8; nt++) {
            int d = d0 + nt * 8 + 2 * cl;
            float cb0 = g_cbias[j][b][d], cb1 = g_cbias[j][b][d + 1];
            uint32_t lo = f16pack((acc[mg][nt][0] + cb0) * s, (acc[mg][nt][1] + cb1) * s);
            uint32_t hi = f16pack((acc[mg][nt][2] + cb0) * s, (acc[mg][nt][3] + cb1) * s);
            *reinterpret_cast<uint32_t*>(dst + ((size_t)(b * P) + p_lo) * C + d) = lo;
            *reinterpret_cast<uint32_t*>(dst + ((size_t)(b * P) + p_lo + 8) * C + d) = hi;
        }
    }
}

// ---------------- kernel 4: flash attention, 32q CTA x 2 warps (16 rows each) ----------------
// SMEM 32KB: 2 K/V buffers (16KB each). Q (4KB) staged in buf0 pre-loop.
#define KVB 16384
#define STOT 32768

__global__ void __launch_bounds__(64, 6) attn_mma(const float* __restrict__ x,
                                                  float* __restrict__ out) {
    __shared__ __align__(128) char smem[STOT];
    uint32_t sb = smem_u32(smem);
    int tid = threadIdx.x;
    int wid = tid >> 5, lane = tid & 31;
    int grp = lane >> 3, lr = lane & 7;
    int head = blockIdx.y;
    int b = head >> 2, h = head & 3;
    int q0 = blockIdx.x * 32;

    const char* qsrc  = (const char*)(g_qb + ((size_t)(b * P) + q0) * C + h * CH);
    const char* kbase = (const char*)(g_kb + (size_t)(b * P) * C + h * CH);
    const char* vbase = (const char*)(g_vb + (size_t)(b * P) * C + h * CH);

    // stage Q (32 rows x 128B = 4KB) into buf0, read fragments, release
#pragma unroll
    for (int it = 0; it < 4; it++) {
        int lin = it * 64 + tid;
        int row = lin >> 3, ch = lin & 7;
        cp16(sb + SWZ(row * 128 + ch * 16), qsrc + (size_t)row * (C * 2) + ch * 16);
    }
    CP_COMMIT();
    CP_WAIT(0);
    __syncthreads();

    uint32_t qa[4][4];
#pragma unroll
    for (int kc = 0; kc < 4; kc++) {
        int row = wid * 16 + ((grp & 1) ? 8 : 0) + lr;
        int col = kc * 16 + ((grp >> 1) ? 8 : 0);
        ldm_x4(qa[kc][0], qa[kc][1], qa[kc][2], qa[kc][3],
               sb + SWZ(row * 128 + col * 2));
    }
    __syncthreads();    // buf0 free

    // issue K/V tiles 0 and 1 (512 chunks per matrix, 64 threads -> 8 iters)
    {
        int row = tid >> 3, ch = tid & 7;   // row 0..7
#pragma unroll
        for (int tt = 0; tt < 2; tt++) {
            uint32_t base = sb + tt * KVB;
            int t0 = tt * KTILE;
#pragma unroll
            for (int qr = 0; qr < 8; qr++) {
                int r = row + qr * 8;
                uint32_t so2 = SWZ(r * 128 + ch * 16);
                cp16(base + so2, kbase + (size_t)(t0 + r) * (C * 2) + ch * 16);
                cp16(base + 8192 + so2, vbase + (size_t)(t0 + r) * (C * 2) + ch * 16);
            }
            CP_COMMIT();
        }
    }

    float o[8][4];
#pragma unroll
    for (int j = 0; j < 8; j++)
#pragma unroll
        for (int i = 0; i < 4; i++) o[j][i] = 0.f;
    float l_lo = 0.f, l_hi = 0.f;

    for (int t = 0; t < NKT; t++) {
        if (t < NKT - 1) { CP_WAIT(1); } else { CP_WAIT(0); }
        __syncthreads();        // tile t resident

        uint32_t ks = sb + (t & 1) * KVB;
        uint32_t vs = ks + 8192;

        // S = Q K^T, f16x2 exp, P fragments
        uint32_t pfr[4][4];
        uint32_t ll = 0, lh = 0;
#pragma unroll
        for (int np = 0; np < 4; np++) {
            float s0[2][4];
#pragma unroll
            for (int i = 0; i < 4; i++) { s0[0][i] = 0.f; s0[1][i] = 0.f; }
#pragma unroll
            for (int kc = 0; kc < 4; kc++) {
                int row = np * 16 + ((grp >> 1) ? 8 : 0) + lr;   // key
                int col = kc * 16 + ((grp & 1) ? 8 : 0);         // d
                uint32_t r0, r1, r2, r3;
                ldm_x4(r0, r1, r2, r3, ks + SWZ(row * 128 + col * 2));
                mma16816(s0[0], qa[kc], r0, r1);
                mma16816(s0[1], qa[kc], r2, r3);
            }
            pfr[np][0] = ex2h2(f16pack(s0[0][0], s0[0][1]));
            pfr[np][1] = ex2h2(f16pack(s0[0][2], s0[0][3]));
            pfr[np][2] = ex2h2(f16pack(s0[1][0], s0[1][1]));
            pfr[np][3] = ex2h2(f16pack(s0[1][2], s0[1][3]));
            ll = hadd2(ll, hadd2(pfr[np][0], pfr[np][2]));
            lh = hadd2(lh, hadd2(pfr[np][1], pfr[np][3]));
        }
        {
            float2 f;
            f = h2f2(ll); l_lo += f.x + f.y;
            f = h2f2(lh); l_hi += f.x + f.y;
        }

        // O += P V
#pragma unroll
        for (int np = 0; np < 4; np++) {
#pragma unroll
            for (int kc = 0; kc < 4; kc++) {
                int row = kc * 16 + ((grp & 1) ? 8 : 0) + lr;    // key
                int col = np * 16 + ((grp >> 1) ? 8 : 0);        // d
                uint32_t r0, r1, r2, r3;
                ldm_x4t(r0, r1, r2, r3, vs + SWZ(row * 128 + col * 2));
                mma16816(o[2 * np],     pfr[kc], r0, r1);
                mma16816(o[2 * np + 1], pfr[kc], r2, r3);
            }
        }

        __syncthreads();        // all warps done reading buf (t&1)
        if (t + 2 < NKT) {
            int t0 = (t + 2) * KTILE;
            uint32_t base = sb + (t & 1) * KVB;   // (t+2)&1 == t&1
            int row = tid >> 3, ch = tid & 7;
#pragma unroll
            for (int qr = 0; qr < 8; qr++) {
                int r = row + qr * 8;
                uint32_t so2 = SWZ(r * 128 + ch * 16);
                cp16(base + so2, kbase + (size_t)(t0 + r) * (C * 2) + ch * 16);
                cp16(base + 8192 + so2, vbase + (size_t)(t0 + r) * (C * 2) + ch * 16);
            }
            CP_COMMIT();
        }
    }

    // reduce l over quad
    l_lo += __shfl_xor_sync(0xFFFFFFFF, l_lo, 1);
    l_lo += __shfl_xor_sync(0xFFFFFFFF, l_lo, 2);
    l_hi += __shfl_xor_sync(0xFFFFFFFF, l_hi, 1);
    l_hi += __shfl_xor_sync(0xFFFFFFFF, l_hi, 2);
    float inv_lo = 1.f / l_lo, inv_hi = 1.f / l_hi;

    // stage O [d][q] into smem (8KB), residual add, coalesced write
    float* so = reinterpret_cast<float*>(smem);   // 64 x 32 f32
    int r_lo = wid * 16 + (lane >> 2);
    int r_hi = r_lo + 8;
    int dc   = 2 * (lane & 3);
#pragma unroll
    for (int j = 0; j < 8; j++) {
        int d = 8 * j + dc;
        so[d * 32 + r_lo]       = o[j][0] * inv_lo;
        so[(d + 1) * 32 + r_lo] = o[j][1] * inv_lo;
        so[d * 32 + r_hi]       = o[j][2] * inv_hi;
        so[(d + 1) * 32 + r_hi] = o[j][3] * inv_hi;
    }
    __syncthreads();

    size_t obase = ((size_t)(b * C) + h * CH) * P + q0;
#pragma unroll
    for (int it = 0; it < 32; it++) {
        int lin = it * 64 + tid;
        int d = lin >> 5, qq = lin & 31;
        size_t idx = obase + (size_t)d * P + qq;
        out[idx] = x[idx] + so[lin];
    }
}

// ---------------- launch ----------------
extern "C" void kernel_launch(void* const* d_in, const int* in_sizes, int n_in,
                              void* d_out, int out_size) {
    const float* x     = (const float*)d_in[0];
    const float* text  = (const float*)d_in[1];
    const float* gamma = (const float*)d_in[2];
    const float* beta  = (const float*)d_in[3];
    const float* W0    = (const float*)d_in[4];
    const float* b0    = (const float*)d_in[5];
    const float* W1    = (const float*)d_in[6];
    const float* b1    = (const float*)d_in[7];
    const float* W2    = (const float*)d_in[8];
    const float* b2    = (const float*)d_in[9];
    float* out = (float*)d_out;

    gn_stats<<<B * G, 256>>>(x, text);
    prep_all<<<1240, 256>>>(x, text, gamma, beta, W0, b0, W1, b1, W2, b2);
    qkv_mma<<<dim3(P / 128, 12, B), 128>>>();
    attn_mma<<<dim3(P / 32, B * NH), 64>>>(x, out);
}